// round 14
// baseline (speedup 1.0000x reference)
#include <cuda_runtime.h>
#include <math.h>

#define NFEAT  128
#define HIDF   128
#define HEADS  4
#define NHID   32
#define NCLASS 40
#define NEGS   0.2f
#define EPSBN  1e-5f
#define MAXN   100000
#define MAXET  1700000   // E (1.6M) + N (100K) self-loops

// ---------------- scratch (static device globals; no allocation) ----------------
__device__ float g_h   [(size_t)MAXN * HIDF];   // projected features (reused as h2 [N,40])
__device__ float g_agg [(size_t)MAXN * HIDF];   // aggregation output / next-layer input
__device__ float g_als [(size_t)MAXN * HEADS];
__device__ float g_ald [(size_t)MAXN * HEADS];
__device__ int   g_rowptr[MAXN + 1];
__device__ int   g_cnt   [MAXN];                // hist buffer / scatter cursor (re-zeroed in histScanK)
__device__ int   g_csrsrc[MAXET];

__device__ __forceinline__ float lrelu(float e) { return e > 0.f ? e : NEGS * e; }

__device__ __forceinline__ float wredmax(float v) {
#pragma unroll
    for (int o = 16; o >= 1; o >>= 1) v = fmaxf(v, __shfl_xor_sync(0xffffffffu, v, o));
    return v;
}
__device__ __forceinline__ float wredsum(float v) {
#pragma unroll
    for (int o = 16; o >= 1; o >>= 1) v += __shfl_xor_sync(0xffffffffu, v, o);
    return v;
}

__device__ __forceinline__ unsigned f2tf(float x) {
    unsigned r;
    asm("cvt.rna.tf32.f32 %0, %1;" : "=r"(r) : "f"(x));
    return r;
}

__device__ __forceinline__ void mma_tf32(float* c, const unsigned* a, const unsigned* b) {
    asm volatile(
        "mma.sync.aligned.m16n8k8.row.col.f32.tf32.tf32.f32 "
        "{%0,%1,%2,%3},{%4,%5,%6,%7},{%8,%9},{%0,%1,%2,%3};"
        : "+f"(c[0]), "+f"(c[1]), "+f"(c[2]), "+f"(c[3])
        : "r"(a[0]), "r"(a[1]), "r"(a[2]), "r"(a[3]), "r"(b[0]), "r"(b[1]));
}

// ---------------- fused single-block CSR front-end: zero cnt -> hist -> scan ----------------
// One 1024-thread block; runs on the side stream hidden under the layer-0 GEMM.
// Leaves rowptr[0..n] valid and cnt[i] = rowptr[i] (scatter cursor).
__global__ void __launch_bounds__(1024, 1)
histScanK(const int* __restrict__ dst, int* __restrict__ cnt, int* __restrict__ rowptr,
          int E, int ET, int n) {
    __shared__ int tsum[1024];
    int t = threadIdx.x;

    // phase 0: zero cnt (previous call left it = rowptr[i+1])
    for (int i = t; i < n; i += 1024) cnt[i] = 0;
    __syncthreads();

    // phase 1: histogram
    for (int i = t; i < ET; i += 1024) {
        int d = (i < E) ? dst[i] : (i - E);
        atomicAdd(&cnt[d], 1);
    }
    __syncthreads();

    // phase 2: blocked exclusive scan; seeds cnt[i] = rowptr[i]
    int C = (n + 1023) >> 10;
    int b = t * C;
    int e = min(b + C, n);
    int s = 0;
    for (int i = b; i < e; i++) s += cnt[i];
    tsum[t] = s;
    __syncthreads();
#pragma unroll
    for (int off = 1; off < 1024; off <<= 1) {
        int t2 = (t >= off) ? tsum[t - off] : 0;
        __syncthreads();
        tsum[t] += t2;
        __syncthreads();
    }
    int run = tsum[t] - s;   // exclusive base
    for (int i = b; i < e; i++) {
        int hv = cnt[i];
        rowptr[i] = run;
        cnt[i] = run;        // cursor (read hv first)
        run += hv;
    }
    if (e == n && b < n) rowptr[n] = run;
}

__global__ void scatterK(const int* __restrict__ src, const int* __restrict__ dst,
                         int* __restrict__ cnt, int* __restrict__ csrsrc, int E, int ET) {
    int i = blockIdx.x * blockDim.x + threadIdx.x;
    int stride = gridDim.x * blockDim.x;
    for (; i < ET; i += stride) {
        int s, d;
        if (i < E) { s = src[i]; d = dst[i]; } else { s = d = i - E; }
        int pos = atomicAdd(&cnt[d], 1);
        csrsrc[pos] = s;
    }
}

// ---------------- tensor-core GEMM (3xTF32) + fused attention logits ----------------
#define KC   16
#define KST  20
__global__ void __launch_bounds__(256, 2)
gemm128_tc(const float* __restrict__ X, const float* __restrict__ W,
           const float* __restrict__ as, const float* __restrict__ ad,
           float* __restrict__ O, float* __restrict__ als, float* __restrict__ ald,
           int n) {
    __shared__ float Ahi[128 * KST], Alo[128 * KST];
    __shared__ float Bhi[128 * KST], Blo[128 * KST];
    __shared__ float asSh[128], adSh[128];

    int t    = threadIdx.x;
    int lane = t & 31;
    int wid  = t >> 5;
    int wm   = wid >> 1;
    int wn   = wid & 1;
    int gid  = lane >> 2;
    int tig  = lane & 3;
    int row0 = blockIdx.x * 128;

    if (t < 128) { asSh[t] = as[t]; adSh[t] = ad[t]; }

    float acc[2][8][4];
#pragma unroll
    for (int i = 0; i < 2; i++)
#pragma unroll
        for (int j = 0; j < 8; j++)
#pragma unroll
            for (int k = 0; k < 4; k++) acc[i][j][k] = 0.f;

    for (int kt = 0; kt < 128; kt += KC) {
#pragma unroll
        for (int half = 0; half < 2; half++) {
            int r  = (t >> 2) + half * 64;
            int kq = (t & 3) * 4;
            int gr = row0 + r;
            float4 xv = (gr < n) ? *(const float4*)(X + (size_t)gr * 128 + kt + kq)
                                 : make_float4(0.f, 0.f, 0.f, 0.f);
            float4 wv = *(const float4*)(W + (size_t)r * 128 + kt + kq);
            float xa[4] = {xv.x, xv.y, xv.z, xv.w};
            float wa[4] = {wv.x, wv.y, wv.z, wv.w};
            float xh[4], xl[4], wh[4], wl[4];
#pragma unroll
            for (int j = 0; j < 4; j++) {
                xh[j] = __uint_as_float(f2tf(xa[j]));
                xl[j] = __uint_as_float(f2tf(xa[j] - xh[j]));
                wh[j] = __uint_as_float(f2tf(wa[j]));
                wl[j] = __uint_as_float(f2tf(wa[j] - wh[j]));
            }
            *(float4*)&Ahi[r * KST + kq] = make_float4(xh[0], xh[1], xh[2], xh[3]);
            *(float4*)&Alo[r * KST + kq] = make_float4(xl[0], xl[1], xl[2], xl[3]);
            *(float4*)&Bhi[r * KST + kq] = make_float4(wh[0], wh[1], wh[2], wh[3]);
            *(float4*)&Blo[r * KST + kq] = make_float4(wl[0], wl[1], wl[2], wl[3]);
        }
        __syncthreads();

#pragma unroll
        for (int ks = 0; ks < KC; ks += 8) {
            unsigned ah[2][4], al[2][4];
#pragma unroll
            for (int tm = 0; tm < 2; tm++) {
                int r = wm * 32 + tm * 16 + gid;
                ah[tm][0] = __float_as_uint(Ahi[r * KST + ks + tig]);
                ah[tm][1] = __float_as_uint(Ahi[(r + 8) * KST + ks + tig]);
                ah[tm][2] = __float_as_uint(Ahi[r * KST + ks + tig + 4]);
                ah[tm][3] = __float_as_uint(Ahi[(r + 8) * KST + ks + tig + 4]);
                al[tm][0] = __float_as_uint(Alo[r * KST + ks + tig]);
                al[tm][1] = __float_as_uint(Alo[(r + 8) * KST + ks + tig]);
                al[tm][2] = __float_as_uint(Alo[r * KST + ks + tig + 4]);
                al[tm][3] = __float_as_uint(Alo[(r + 8) * KST + ks + tig + 4]);
            }
            unsigned bh[8][2], bl[8][2];
#pragma unroll
            for (int tn = 0; tn < 8; tn++) {
                int c = wn * 64 + tn * 8 + gid;
                bh[tn][0] = __float_as_uint(Bhi[c * KST + ks + tig]);
                bh[tn][1] = __float_as_uint(Bhi[c * KST + ks + tig + 4]);
                bl[tn][0] = __float_as_uint(Blo[c * KST + ks + tig]);
                bl[tn][1] = __float_as_uint(Blo[c * KST + ks + tig + 4]);
            }
            // term-outer ordering: consecutive MMAs target different accumulators
#pragma unroll
            for (int tm = 0; tm < 2; tm++)
#pragma unroll
                for (int tn = 0; tn < 8; tn++)
                    mma_tf32(acc[tm][tn], ah[tm], bh[tn]);
#pragma unroll
            for (int tm = 0; tm < 2; tm++)
#pragma unroll
                for (int tn = 0; tn < 8; tn++)
                    mma_tf32(acc[tm][tn], ah[tm], bl[tn]);
#pragma unroll
            for (int tm = 0; tm < 2; tm++)
#pragma unroll
                for (int tn = 0; tn < 8; tn++)
                    mma_tf32(acc[tm][tn], al[tm], bh[tn]);
        }
        __syncthreads();
    }

    // store O
#pragma unroll
    for (int tm = 0; tm < 2; tm++) {
        int r = row0 + wm * 32 + tm * 16 + gid;
#pragma unroll
        for (int tn = 0; tn < 8; tn++) {
            int c = wn * 64 + tn * 8 + 2 * tig;
            if (r < n)
                *(float2*)(O + (size_t)r * 128 + c) = make_float2(acc[tm][tn][0], acc[tm][tn][1]);
            if (r + 8 < n)
                *(float2*)(O + (size_t)(r + 8) * 128 + c) = make_float2(acc[tm][tn][2], acc[tm][tn][3]);
        }
    }

    // fused attention logits: warp wn owns heads {2wn, 2wn+1}
    float ps[2][4], pd[2][4];
#pragma unroll
    for (int j = 0; j < 2; j++)
#pragma unroll
        for (int sl = 0; sl < 4; sl++) { ps[j][sl] = 0.f; pd[j][sl] = 0.f; }
#pragma unroll
    for (int tm = 0; tm < 2; tm++)
#pragma unroll
        for (int tn = 0; tn < 8; tn++) {
            int j = tn >> 2;
            int c = wn * 64 + tn * 8 + 2 * tig;
            float a0 = asSh[c], a1 = asSh[c + 1];
            float d0 = adSh[c], d1 = adSh[c + 1];
            ps[j][tm * 2 + 0] += acc[tm][tn][0] * a0 + acc[tm][tn][1] * a1;
            ps[j][tm * 2 + 1] += acc[tm][tn][2] * a0 + acc[tm][tn][3] * a1;
            pd[j][tm * 2 + 0] += acc[tm][tn][0] * d0 + acc[tm][tn][1] * d1;
            pd[j][tm * 2 + 1] += acc[tm][tn][2] * d0 + acc[tm][tn][3] * d1;
        }
#pragma unroll
    for (int j = 0; j < 2; j++)
#pragma unroll
        for (int sl = 0; sl < 4; sl++) {
            ps[j][sl] += __shfl_xor_sync(0xffffffffu, ps[j][sl], 1);
            ps[j][sl] += __shfl_xor_sync(0xffffffffu, ps[j][sl], 2);
            pd[j][sl] += __shfl_xor_sync(0xffffffffu, pd[j][sl], 1);
            pd[j][sl] += __shfl_xor_sync(0xffffffffu, pd[j][sl], 2);
        }
    if (tig == 0) {
#pragma unroll
        for (int sl = 0; sl < 4; sl++) {
            int r = row0 + wm * 32 + (sl >> 1) * 16 + (sl & 1) * 8 + gid;
            if (r < n) {
#pragma unroll
                for (int j = 0; j < 2; j++) {
                    als[(size_t)r * 4 + 2 * wn + j] = ps[j][sl];
                    ald[(size_t)r * 4 + 2 * wn + j] = pd[j][sl];
                }
            }
        }
    }
}

// ---------------- fused GAT edge stage, 4 heads — single pass, direct gather (R8-best, FROZEN) ----------------
__global__ void __launch_bounds__(512)
gat_edge4(const int* __restrict__ rowptr, const int* __restrict__ csrsrc,
          const float* __restrict__ als, const float* __restrict__ ald,
          const float* __restrict__ h, float* __restrict__ out,
          const float* __restrict__ bias, const float* __restrict__ gam,
          const float* __restrict__ bet, const float* __restrict__ mu,
          const float* __restrict__ var, int n) {
    int lane = threadIdx.x & 31;
    int d = (blockIdx.x * blockDim.x + threadIdx.x) >> 5;
    if (d >= n) return;

    int start = rowptr[d], end = rowptr[d + 1];
    float4 bld = ((const float4*)ald)[d];
    int head = lane >> 3;
    float bh = (head == 0) ? bld.x : (head == 1) ? bld.y : (head == 2) ? bld.z : bld.w;

    float4 acc = make_float4(0.f, 0.f, 0.f, 0.f);
    float sw = 0.f;
#pragma unroll 8
    for (int e = start; e < end; e++) {
        int s = csrsrc[e];                              // broadcast (same addr all lanes)
        float av = __ldg(als + (size_t)s * 4 + head);   // broadcast per 8 lanes
        float w = __expf(lrelu(av + bh));
        sw += w;
        float4 hv = ((const float4*)h)[(size_t)s * 32 + lane];
        acc.x += w * hv.x; acc.y += w * hv.y;
        acc.z += w * hv.z; acc.w += w * hv.w;
    }
    float inv = __frcp_rn(sw);

    // epilogue: normalize, +bias, BN(eval), ReLU
    float4 bb = ((const float4*)bias)[lane];
    float4 gg = ((const float4*)gam)[lane];
    float4 be = ((const float4*)bet)[lane];
    float4 mm = ((const float4*)mu)[lane];
    float4 vv = ((const float4*)var)[lane];
    float4 o;
    o.x = (acc.x * inv + bb.x - mm.x) * rsqrtf(vv.x + EPSBN) * gg.x + be.x;
    o.y = (acc.y * inv + bb.y - mm.y) * rsqrtf(vv.y + EPSBN) * gg.y + be.y;
    o.z = (acc.z * inv + bb.z - mm.z) * rsqrtf(vv.z + EPSBN) * gg.z + be.z;
    o.w = (acc.w * inv + bb.w - mm.w) * rsqrtf(vv.w + EPSBN) * gg.w + be.w;
    o.x = fmaxf(o.x, 0.f); o.y = fmaxf(o.y, 0.f);
    o.z = fmaxf(o.z, 0.f); o.w = fmaxf(o.w, 0.f);
    ((float4*)(out + (size_t)d * 128))[lane] = o;
}

// ---------------- layer-2 GEMM (128 -> 40) fused with attention logits, float4 LDS ----------------
__global__ void gemm40(const float* __restrict__ X, const float* __restrict__ W,
                       const float* __restrict__ as2, const float* __restrict__ ad2,
                       float* __restrict__ H2, float* __restrict__ als,
                       float* __restrict__ ald, int n) {
    __shared__ float Ws[NCLASS][132];
    __shared__ float asS[NCLASS], adS[NCLASS];
    __shared__ float xs[8][128];
    int t = threadIdx.x;
    for (int i = t; i < NCLASS * 128; i += blockDim.x) {
        int c = i >> 7, k = i & 127;
        Ws[c][k] = W[i];
    }
    if (t < NCLASS) { asS[t] = as2[t]; adS[t] = ad2[t]; }
    __syncthreads();

    int wid = t >> 5, lane = t & 31;
    int wtotal = (gridDim.x * blockDim.x) >> 5;
    for (int row = blockIdx.x * 8 + wid; row < n; row += wtotal) {
        float4 xv = ((const float4*)(X + (size_t)row * 128))[lane];
        ((float4*)xs[wid])[lane] = xv;
        __syncwarp();
        float acc0 = 0.f, acc1 = 0.f;
        int c0 = lane, c1 = 32 + lane;
#pragma unroll
        for (int k = 0; k < 128; k += 4) {
            float4 xk = *(const float4*)&xs[wid][k];
            float4 w0 = *(const float4*)&Ws[c0][k];
            acc0 += xk.x * w0.x + xk.y * w0.y + xk.z * w0.z + xk.w * w0.w;
            if (lane < 8) {
                float4 w1 = *(const float4*)&Ws[c1][k];
                acc1 += xk.x * w1.x + xk.y * w1.y + xk.z * w1.z + xk.w * w1.w;
            }
        }
        H2[(size_t)row * NCLASS + c0] = acc0;
        if (lane < 8) H2[(size_t)row * NCLASS + c1] = acc1;
        float ps = acc0 * asS[c0] + (lane < 8 ? acc1 * asS[c1] : 0.f);
        float pd = acc0 * adS[c0] + (lane < 8 ? acc1 * adS[c1] : 0.f);
        ps = wredsum(ps);
        pd = wredsum(pd);
        if (lane == 0) { als[row] = ps; ald[row] = pd; }
        __syncwarp();
    }
}

// ---------------- fused layer-2 edge stage (1 head) — single pass + bias + log_softmax ----------------
__global__ void __launch_bounds__(512)
gat_edge1(const int* __restrict__ rowptr, const int* __restrict__ csrsrc,
          const float* __restrict__ als, const float* __restrict__ ald,
          const float* __restrict__ h2, const float* __restrict__ b2,
          float* __restrict__ out, int n) {
    int lane = threadIdx.x & 31;
    int d = (blockIdx.x * blockDim.x + threadIdx.x) >> 5;
    if (d >= n) return;

    int start = rowptr[d], end = rowptr[d + 1];
    float bld = ald[d];

    float acc0 = 0.f, acc1 = 0.f, sw = 0.f;
#pragma unroll 8
    for (int e = start; e < end; e++) {
        int s = csrsrc[e];                       // broadcast
        float w = __expf(lrelu(als[s] + bld));
        sw += w;
        const float* row = h2 + (size_t)s * NCLASS;
        acc0 += w * row[lane];
        if (lane < 8) acc1 += w * row[32 + lane];
    }
    float inv = __frcp_rn(sw);

    // bias + log_softmax
    float x0 = acc0 * inv + b2[lane];
    float x1 = (lane < 8) ? acc1 * inv + b2[32 + lane] : -3.4e38f;
    float m = wredmax(fmaxf(x0, x1));
    float s = __expf(x0 - m) + (lane < 8 ? __expf(x1 - m) : 0.f);
    s = wredsum(s);
    float lse = logf(s);
    float* orow = out + (size_t)d * NCLASS;
    orow[lane] = x0 - m - lse;
    if (lane < 8) orow[32 + lane] = x1 - m - lse;
}

// ---------------- host ----------------
extern "C" void kernel_launch(void* const* d_in, const int* in_sizes, int n_in,
                              void* d_out, int out_size) {
    const float* x   = (const float*)d_in[0];
    const int*   ei  = (const int*)d_in[1];
    const float* W0  = (const float*)d_in[2];
    const float* as0 = (const float*)d_in[3];
    const float* ad0 = (const float*)d_in[4];
    const float* b0  = (const float*)d_in[5];
    const float* g0  = (const float*)d_in[6];
    const float* be0 = (const float*)d_in[7];
    const float* m0  = (const float*)d_in[8];
    const float* v0  = (const float*)d_in[9];
    const float* W1  = (const float*)d_in[10];
    const float* as1 = (const float*)d_in[11];
    const float* ad1 = (const float*)d_in[12];
    const float* b1  = (const float*)d_in[13];
    const float* g1  = (const float*)d_in[14];
    const float* be1 = (const float*)d_in[15];
    const float* m1  = (const float*)d_in[16];
    const float* v1  = (const float*)d_in[17];
    const float* W2  = (const float*)d_in[18];
    const float* as2 = (const float*)d_in[19];
    const float* ad2 = (const float*)d_in[20];
    const float* b2  = (const float*)d_in[21];

    int n  = in_sizes[0] / NFEAT;
    int E  = in_sizes[1] / 2;
    int ET = E + n;

    float *h, *agg, *als, *ald;
    int *rowptr, *cnt, *csrsrc;
    cudaGetSymbolAddress((void**)&h, g_h);
    cudaGetSymbolAddress((void**)&agg, g_agg);
    cudaGetSymbolAddress((void**)&als, g_als);
    cudaGetSymbolAddress((void**)&ald, g_ald);
    cudaGetSymbolAddress((void**)&rowptr, g_rowptr);
    cudaGetSymbolAddress((void**)&cnt, g_cnt);
    cudaGetSymbolAddress((void**)&csrsrc, g_csrsrc);

    // lazily-created side stream + fork/join events (resources, not device memory)
    static cudaStream_t s2 = 0;
    static cudaEvent_t evFork = 0, evJoin = 0;
    if (!s2) {
        cudaStreamCreateWithFlags(&s2, cudaStreamNonBlocking);
        cudaEventCreateWithFlags(&evFork, cudaEventDisableTiming);
        cudaEventCreateWithFlags(&evJoin, cudaEventDisableTiming);
    }

    const int gb  = (n + 127) / 128;           // gemm blocks
    const int ab5 = (n + 15) / 16;             // warp-per-node blocks (512 thr)
    const int eb  = (ET + 255) / 256;          // thread-per-edge blocks

    // ---------------- CSR build on side stream (2 launches), overlapped with layer-0 GEMM ----------------
    cudaEventRecord(evFork, 0);
    cudaStreamWaitEvent(s2, evFork, 0);
    histScanK<<<1, 1024, 0, s2>>>(ei + E, cnt, rowptr, E, ET, n);          // launch 1
    scatterK <<<eb, 256, 0, s2>>>(ei, ei + E, cnt, csrsrc, E, ET);         // launch 2
    cudaEventRecord(evJoin, s2);

    // ---------------- layer 0 (main stream, runs concurrently with CSR) ----------------
    gemm128_tc<<<gb, 256>>>(x, W0, as0, ad0, h, als, ald, n);              // launch 3
    cudaStreamWaitEvent(0, evJoin, 0);
    gat_edge4<<<ab5, 512>>>(rowptr, csrsrc, als, ald, h, agg,              // launch 4 (ncu target)
                            b0, g0, be0, m0, v0, n);

    // ---------------- layer 1 ----------------
    gemm128_tc<<<gb, 256>>>(agg, W1, as1, ad1, h, als, ald, n);
    gat_edge4<<<ab5, 512>>>(rowptr, csrsrc, als, ald, h, agg, b1, g1, be1, m1, v1, n);

    // ---------------- layer 2 (heads=1, 40 classes) ----------------
    gemm40<<<1184, 256>>>(agg, W2, as2, ad2, h, als, ald, n);
    gat_edge1<<<ab5, 512>>>(rowptr, csrsrc, als, ald, h, b2, (float*)d_out, n);
}

// round 16
// speedup vs baseline: 2.1344x; 2.1344x over previous
#include <cuda_runtime.h>
#include <math.h>

#define NFEAT  128
#define HIDF   128
#define HEADS  4
#define NHID   32
#define NCLASS 40
#define NEGS   0.2f
#define EPSBN  1e-5f
#define MAXN   100000
#define MAXET  1700000   // E (1.6M) + N (100K) self-loops

// ---------------- scratch (static device globals; no allocation) ----------------
__device__ float g_h   [(size_t)MAXN * HIDF];   // projected features (reused as h2 [N,40])
__device__ float g_agg [(size_t)MAXN * HIDF];   // aggregation output / next-layer input
__device__ float g_als [(size_t)MAXN * HEADS];
__device__ float g_ald [(size_t)MAXN * HEADS];
__device__ int   g_rowptr[MAXN + 1];
__device__ int   g_cnt   [MAXN];                // hist buffer / scatter cursor (zeroed by zki at call end)
__device__ int   g_csrsrc[MAXET];

__device__ __forceinline__ float lrelu(float e) { return e > 0.f ? e : NEGS * e; }

__device__ __forceinline__ float wredmax(float v) {
#pragma unroll
    for (int o = 16; o >= 1; o >>= 1) v = fmaxf(v, __shfl_xor_sync(0xffffffffu, v, o));
    return v;
}
__device__ __forceinline__ float wredsum(float v) {
#pragma unroll
    for (int o = 16; o >= 1; o >>= 1) v += __shfl_xor_sync(0xffffffffu, v, o);
    return v;
}

__device__ __forceinline__ unsigned f2tf(float x) {
    unsigned r;
    asm("cvt.rna.tf32.f32 %0, %1;" : "=r"(r) : "f"(x));
    return r;
}

__device__ __forceinline__ void mma_tf32(float* c, const unsigned* a, const unsigned* b) {
    asm volatile(
        "mma.sync.aligned.m16n8k8.row.col.f32.tf32.tf32.f32 "
        "{%0,%1,%2,%3},{%4,%5,%6,%7},{%8,%9},{%0,%1,%2,%3};"
        : "+f"(c[0]), "+f"(c[1]), "+f"(c[2]), "+f"(c[3])
        : "r"(a[0]), "r"(a[1]), "r"(a[2]), "r"(a[3]), "r"(b[0]), "r"(b[1]));
}

// ---------------- zero fill (ints) ----------------
__global__ void zki(int* __restrict__ p, int cnt) {
    int i = blockIdx.x * blockDim.x + threadIdx.x;
    int stride = gridDim.x * blockDim.x;
    for (; i < cnt; i += stride) p[i] = 0;
}

// ---------------- CSR build (multi-block, proven) ----------------
__global__ void histK(const int* __restrict__ dst, int* __restrict__ hist, int E, int ET) {
    int i = blockIdx.x * blockDim.x + threadIdx.x;
    int stride = gridDim.x * blockDim.x;
    for (; i < ET; i += stride) {
        int d = (i < E) ? dst[i] : (i - E);
        atomicAdd(&hist[d], 1);
    }
}

// single-block blocked exclusive scan; writes rowptr[0..n] and seeds cnt[i]=rowptr[i].
__global__ void scanAll(const int* __restrict__ hist, int* __restrict__ rowptr,
                        int* __restrict__ cnt, int n) {
    __shared__ int tsum[1024];
    int t = threadIdx.x;
    int C = (n + 1023) >> 10;
    int b = t * C;
    int e = min(b + C, n);
    int s = 0;
    for (int i = b; i < e; i++) s += hist[i];
    tsum[t] = s;
    __syncthreads();
#pragma unroll
    for (int off = 1; off < 1024; off <<= 1) {
        int t2 = (t >= off) ? tsum[t - off] : 0;
        __syncthreads();
        tsum[t] += t2;
        __syncthreads();
    }
    int run = tsum[t] - s;   // exclusive base
    for (int i = b; i < e; i++) {
        int hv = hist[i];
        rowptr[i] = run;
        cnt[i] = run;        // aliases hist; read hv first
        run += hv;
    }
    if (e == n && b < n) rowptr[n] = run;
}

__global__ void scatterK(const int* __restrict__ src, const int* __restrict__ dst,
                         int* __restrict__ cnt, int* __restrict__ csrsrc, int E, int ET) {
    int i = blockIdx.x * blockDim.x + threadIdx.x;
    int stride = gridDim.x * blockDim.x;
    for (; i < ET; i += stride) {
        int s, d;
        if (i < E) { s = src[i]; d = dst[i]; } else { s = d = i - E; }
        int pos = atomicAdd(&cnt[d], 1);
        csrsrc[pos] = s;
    }
}

// ---------------- tensor-core GEMM (3xTF32) + fused attention logits ----------------
#define KC   16
#define KST  20
__global__ void __launch_bounds__(256, 2)
gemm128_tc(const float* __restrict__ X, const float* __restrict__ W,
           const float* __restrict__ as, const float* __restrict__ ad,
           float* __restrict__ O, float* __restrict__ als, float* __restrict__ ald,
           int n) {
    __shared__ float Ahi[128 * KST], Alo[128 * KST];
    __shared__ float Bhi[128 * KST], Blo[128 * KST];
    __shared__ float asSh[128], adSh[128];

    int t    = threadIdx.x;
    int lane = t & 31;
    int wid  = t >> 5;
    int wm   = wid >> 1;
    int wn   = wid & 1;
    int gid  = lane >> 2;
    int tig  = lane & 3;
    int row0 = blockIdx.x * 128;

    if (t < 128) { asSh[t] = as[t]; adSh[t] = ad[t]; }

    float acc[2][8][4];
#pragma unroll
    for (int i = 0; i < 2; i++)
#pragma unroll
        for (int j = 0; j < 8; j++)
#pragma unroll
            for (int k = 0; k < 4; k++) acc[i][j][k] = 0.f;

    for (int kt = 0; kt < 128; kt += KC) {
#pragma unroll
        for (int half = 0; half < 2; half++) {
            int r  = (t >> 2) + half * 64;
            int kq = (t & 3) * 4;
            int gr = row0 + r;
            float4 xv = (gr < n) ? *(const float4*)(X + (size_t)gr * 128 + kt + kq)
                                 : make_float4(0.f, 0.f, 0.f, 0.f);
            float4 wv = *(const float4*)(W + (size_t)r * 128 + kt + kq);
            float xa[4] = {xv.x, xv.y, xv.z, xv.w};
            float wa[4] = {wv.x, wv.y, wv.z, wv.w};
            float xh[4], xl[4], wh[4], wl[4];
#pragma unroll
            for (int j = 0; j < 4; j++) {
                xh[j] = __uint_as_float(f2tf(xa[j]));
                xl[j] = __uint_as_float(f2tf(xa[j] - xh[j]));
                wh[j] = __uint_as_float(f2tf(wa[j]));
                wl[j] = __uint_as_float(f2tf(wa[j] - wh[j]));
            }
            *(float4*)&Ahi[r * KST + kq] = make_float4(xh[0], xh[1], xh[2], xh[3]);
            *(float4*)&Alo[r * KST + kq] = make_float4(xl[0], xl[1], xl[2], xl[3]);
            *(float4*)&Bhi[r * KST + kq] = make_float4(wh[0], wh[1], wh[2], wh[3]);
            *(float4*)&Blo[r * KST + kq] = make_float4(wl[0], wl[1], wl[2], wl[3]);
        }
        __syncthreads();

#pragma unroll
        for (int ks = 0; ks < KC; ks += 8) {
            unsigned ah[2][4], al[2][4];
#pragma unroll
            for (int tm = 0; tm < 2; tm++) {
                int r = wm * 32 + tm * 16 + gid;
                ah[tm][0] = __float_as_uint(Ahi[r * KST + ks + tig]);
                ah[tm][1] = __float_as_uint(Ahi[(r + 8) * KST + ks + tig]);
                ah[tm][2] = __float_as_uint(Ahi[r * KST + ks + tig + 4]);
                ah[tm][3] = __float_as_uint(Ahi[(r + 8) * KST + ks + tig + 4]);
                al[tm][0] = __float_as_uint(Alo[r * KST + ks + tig]);
                al[tm][1] = __float_as_uint(Alo[(r + 8) * KST + ks + tig]);
                al[tm][2] = __float_as_uint(Alo[r * KST + ks + tig + 4]);
                al[tm][3] = __float_as_uint(Alo[(r + 8) * KST + ks + tig + 4]);
            }
            unsigned bh[8][2], bl[8][2];
#pragma unroll
            for (int tn = 0; tn < 8; tn++) {
                int c = wn * 64 + tn * 8 + gid;
                bh[tn][0] = __float_as_uint(Bhi[c * KST + ks + tig]);
                bh[tn][1] = __float_as_uint(Bhi[c * KST + ks + tig + 4]);
                bl[tn][0] = __float_as_uint(Blo[c * KST + ks + tig]);
                bl[tn][1] = __float_as_uint(Blo[c * KST + ks + tig + 4]);
            }
            // term-outer ordering: consecutive MMAs target different accumulators
#pragma unroll
            for (int tm = 0; tm < 2; tm++)
#pragma unroll
                for (int tn = 0; tn < 8; tn++)
                    mma_tf32(acc[tm][tn], ah[tm], bh[tn]);
#pragma unroll
            for (int tm = 0; tm < 2; tm++)
#pragma unroll
                for (int tn = 0; tn < 8; tn++)
                    mma_tf32(acc[tm][tn], ah[tm], bl[tn]);
#pragma unroll
            for (int tm = 0; tm < 2; tm++)
#pragma unroll
                for (int tn = 0; tn < 8; tn++)
                    mma_tf32(acc[tm][tn], al[tm], bh[tn]);
        }
        __syncthreads();
    }

    // store O
#pragma unroll
    for (int tm = 0; tm < 2; tm++) {
        int r = row0 + wm * 32 + tm * 16 + gid;
#pragma unroll
        for (int tn = 0; tn < 8; tn++) {
            int c = wn * 64 + tn * 8 + 2 * tig;
            if (r < n)
                *(float2*)(O + (size_t)r * 128 + c) = make_float2(acc[tm][tn][0], acc[tm][tn][1]);
            if (r + 8 < n)
                *(float2*)(O + (size_t)(r + 8) * 128 + c) = make_float2(acc[tm][tn][2], acc[tm][tn][3]);
        }
    }

    // fused attention logits: warp wn owns heads {2wn, 2wn+1}
    float ps[2][4], pd[2][4];
#pragma unroll
    for (int j = 0; j < 2; j++)
#pragma unroll
        for (int sl = 0; sl < 4; sl++) { ps[j][sl] = 0.f; pd[j][sl] = 0.f; }
#pragma unroll
    for (int tm = 0; tm < 2; tm++)
#pragma unroll
        for (int tn = 0; tn < 8; tn++) {
            int j = tn >> 2;
            int c = wn * 64 + tn * 8 + 2 * tig;
            float a0 = asSh[c], a1 = asSh[c + 1];
            float d0 = adSh[c], d1 = adSh[c + 1];
            ps[j][tm * 2 + 0] += acc[tm][tn][0] * a0 + acc[tm][tn][1] * a1;
            ps[j][tm * 2 + 1] += acc[tm][tn][2] * a0 + acc[tm][tn][3] * a1;
            pd[j][tm * 2 + 0] += acc[tm][tn][0] * d0 + acc[tm][tn][1] * d1;
            pd[j][tm * 2 + 1] += acc[tm][tn][2] * d0 + acc[tm][tn][3] * d1;
        }
#pragma unroll
    for (int j = 0; j < 2; j++)
#pragma unroll
        for (int sl = 0; sl < 4; sl++) {
            ps[j][sl] += __shfl_xor_sync(0xffffffffu, ps[j][sl], 1);
            ps[j][sl] += __shfl_xor_sync(0xffffffffu, ps[j][sl], 2);
            pd[j][sl] += __shfl_xor_sync(0xffffffffu, pd[j][sl], 1);
            pd[j][sl] += __shfl_xor_sync(0xffffffffu, pd[j][sl], 2);
        }
    if (tig == 0) {
#pragma unroll
        for (int sl = 0; sl < 4; sl++) {
            int r = row0 + wm * 32 + (sl >> 1) * 16 + (sl & 1) * 8 + gid;
            if (r < n) {
#pragma unroll
                for (int j = 0; j < 2; j++) {
                    als[(size_t)r * 4 + 2 * wn + j] = ps[j][sl];
                    ald[(size_t)r * 4 + 2 * wn + j] = pd[j][sl];
                }
            }
        }
    }
}

// ---------------- fused GAT edge stage, 4 heads — at the LTS gather floor (FROZEN) ----------------
__global__ void __launch_bounds__(512)
gat_edge4(const int* __restrict__ rowptr, const int* __restrict__ csrsrc,
          const float* __restrict__ als, const float* __restrict__ ald,
          const float* __restrict__ h, float* __restrict__ out,
          const float* __restrict__ bias, const float* __restrict__ gam,
          const float* __restrict__ bet, const float* __restrict__ mu,
          const float* __restrict__ var, int n) {
    int lane = threadIdx.x & 31;
    int d = (blockIdx.x * blockDim.x + threadIdx.x) >> 5;
    if (d >= n) return;

    int start = rowptr[d], end = rowptr[d + 1];
    float4 bld = ((const float4*)ald)[d];
    int head = lane >> 3;
    float bh = (head == 0) ? bld.x : (head == 1) ? bld.y : (head == 2) ? bld.z : bld.w;

    float4 acc = make_float4(0.f, 0.f, 0.f, 0.f);
    float sw = 0.f;
#pragma unroll 8
    for (int e = start; e < end; e++) {
        int s = csrsrc[e];                              // broadcast (same addr all lanes)
        float av = __ldg(als + (size_t)s * 4 + head);   // broadcast per 8 lanes
        float w = __expf(lrelu(av + bh));
        sw += w;
        float4 hv = ((const float4*)h)[(size_t)s * 32 + lane];
        acc.x += w * hv.x; acc.y += w * hv.y;
        acc.z += w * hv.z; acc.w += w * hv.w;
    }
    float inv = __frcp_rn(sw);

    // epilogue: normalize, +bias, BN(eval), ReLU
    float4 bb = ((const float4*)bias)[lane];
    float4 gg = ((const float4*)gam)[lane];
    float4 be = ((const float4*)bet)[lane];
    float4 mm = ((const float4*)mu)[lane];
    float4 vv = ((const float4*)var)[lane];
    float4 o;
    o.x = (acc.x * inv + bb.x - mm.x) * rsqrtf(vv.x + EPSBN) * gg.x + be.x;
    o.y = (acc.y * inv + bb.y - mm.y) * rsqrtf(vv.y + EPSBN) * gg.y + be.y;
    o.z = (acc.z * inv + bb.z - mm.z) * rsqrtf(vv.z + EPSBN) * gg.z + be.z;
    o.w = (acc.w * inv + bb.w - mm.w) * rsqrtf(vv.w + EPSBN) * gg.w + be.w;
    o.x = fmaxf(o.x, 0.f); o.y = fmaxf(o.y, 0.f);
    o.z = fmaxf(o.z, 0.f); o.w = fmaxf(o.w, 0.f);
    ((float4*)(out + (size_t)d * 128))[lane] = o;
}

// ---------------- layer-2 GEMM (128 -> 40) fused with attention logits, float4 LDS ----------------
__global__ void gemm40(const float* __restrict__ X, const float* __restrict__ W,
                       const float* __restrict__ as2, const float* __restrict__ ad2,
                       float* __restrict__ H2, float* __restrict__ als,
                       float* __restrict__ ald, int n) {
    __shared__ float Ws[NCLASS][132];
    __shared__ float asS[NCLASS], adS[NCLASS];
    __shared__ float xs[8][128];
    int t = threadIdx.x;
    for (int i = t; i < NCLASS * 128; i += blockDim.x) {
        int c = i >> 7, k = i & 127;
        Ws[c][k] = W[i];
    }
    if (t < NCLASS) { asS[t] = as2[t]; adS[t] = ad2[t]; }
    __syncthreads();

    int wid = t >> 5, lane = t & 31;
    int wtotal = (gridDim.x * blockDim.x) >> 5;
    for (int row = blockIdx.x * 8 + wid; row < n; row += wtotal) {
        float4 xv = ((const float4*)(X + (size_t)row * 128))[lane];
        ((float4*)xs[wid])[lane] = xv;
        __syncwarp();
        float acc0 = 0.f, acc1 = 0.f;
        int c0 = lane, c1 = 32 + lane;
#pragma unroll
        for (int k = 0; k < 128; k += 4) {
            float4 xk = *(const float4*)&xs[wid][k];
            float4 w0 = *(const float4*)&Ws[c0][k];
            acc0 += xk.x * w0.x + xk.y * w0.y + xk.z * w0.z + xk.w * w0.w;
            if (lane < 8) {
                float4 w1 = *(const float4*)&Ws[c1][k];
                acc1 += xk.x * w1.x + xk.y * w1.y + xk.z * w1.z + xk.w * w1.w;
            }
        }
        H2[(size_t)row * NCLASS + c0] = acc0;
        if (lane < 8) H2[(size_t)row * NCLASS + c1] = acc1;
        float ps = acc0 * asS[c0] + (lane < 8 ? acc1 * asS[c1] : 0.f);
        float pd = acc0 * adS[c0] + (lane < 8 ? acc1 * adS[c1] : 0.f);
        ps = wredsum(ps);
        pd = wredsum(pd);
        if (lane == 0) { als[row] = ps; ald[row] = pd; }
        __syncwarp();
    }
}

// ---------------- fused layer-2 edge stage (1 head) — single pass + bias + log_softmax ----------------
__global__ void __launch_bounds__(512)
gat_edge1(const int* __restrict__ rowptr, const int* __restrict__ csrsrc,
          const float* __restrict__ als, const float* __restrict__ ald,
          const float* __restrict__ h2, const float* __restrict__ b2,
          float* __restrict__ out, int n) {
    int lane = threadIdx.x & 31;
    int d = (blockIdx.x * blockDim.x + threadIdx.x) >> 5;
    if (d >= n) return;

    int start = rowptr[d], end = rowptr[d + 1];
    float bld = ald[d];

    float acc0 = 0.f, acc1 = 0.f, sw = 0.f;
#pragma unroll 8
    for (int e = start; e < end; e++) {
        int s = csrsrc[e];                       // broadcast
        float w = __expf(lrelu(als[s] + bld));
        sw += w;
        const float* row = h2 + (size_t)s * NCLASS;
        acc0 += w * row[lane];
        if (lane < 8) acc1 += w * row[32 + lane];
    }
    float inv = __frcp_rn(sw);

    // bias + log_softmax
    float x0 = acc0 * inv + b2[lane];
    float x1 = (lane < 8) ? acc1 * inv + b2[32 + lane] : -3.4e38f;
    float m = wredmax(fmaxf(x0, x1));
    float s = __expf(x0 - m) + (lane < 8 ? __expf(x1 - m) : 0.f);
    s = wredsum(s);
    float lse = logf(s);
    float* orow = out + (size_t)d * NCLASS;
    orow[lane] = x0 - m - lse;
    if (lane < 8) orow[32 + lane] = x1 - m - lse;
}

// ---------------- host ----------------
extern "C" void kernel_launch(void* const* d_in, const int* in_sizes, int n_in,
                              void* d_out, int out_size) {
    const float* x   = (const float*)d_in[0];
    const int*   ei  = (const int*)d_in[1];
    const float* W0  = (const float*)d_in[2];
    const float* as0 = (const float*)d_in[3];
    const float* ad0 = (const float*)d_in[4];
    const float* b0  = (const float*)d_in[5];
    const float* g0  = (const float*)d_in[6];
    const float* be0 = (const float*)d_in[7];
    const float* m0  = (const float*)d_in[8];
    const float* v0  = (const float*)d_in[9];
    const float* W1  = (const float*)d_in[10];
    const float* as1 = (const float*)d_in[11];
    const float* ad1 = (const float*)d_in[12];
    const float* b1  = (const float*)d_in[13];
    const float* g1  = (const float*)d_in[14];
    const float* be1 = (const float*)d_in[15];
    const float* m1  = (const float*)d_in[16];
    const float* v1  = (const float*)d_in[17];
    const float* W2  = (const float*)d_in[18];
    const float* as2 = (const float*)d_in[19];
    const float* ad2 = (const float*)d_in[20];
    const float* b2  = (const float*)d_in[21];

    int n  = in_sizes[0] / NFEAT;
    int E  = in_sizes[1] / 2;
    int ET = E + n;

    float *h, *agg, *als, *ald;
    int *rowptr, *cnt, *csrsrc;
    cudaGetSymbolAddress((void**)&h, g_h);
    cudaGetSymbolAddress((void**)&agg, g_agg);
    cudaGetSymbolAddress((void**)&als, g_als);
    cudaGetSymbolAddress((void**)&ald, g_ald);
    cudaGetSymbolAddress((void**)&rowptr, g_rowptr);
    cudaGetSymbolAddress((void**)&cnt, g_cnt);
    cudaGetSymbolAddress((void**)&csrsrc, g_csrsrc);

    // lazily-created side stream + fork/join events (resources, not device memory)
    static cudaStream_t s2 = 0;
    static cudaEvent_t evFork = 0, evJoin = 0;
    if (!s2) {
        cudaStreamCreateWithFlags(&s2, cudaStreamNonBlocking);
        cudaEventCreateWithFlags(&evFork, cudaEventDisableTiming);
        cudaEventCreateWithFlags(&evJoin, cudaEventDisableTiming);
    }

    const int gb  = (n + 127) / 128;           // gemm blocks
    const int ab5 = (n + 15) / 16;             // warp-per-node blocks (512 thr)
    const int eb  = (ET + 255) / 256;          // thread-per-edge blocks
    const int cb  = (n + 255) / 256;

    // ---------------- CSR build on side stream (multi-block), overlapped with layer-0 GEMM ----------------
    // cnt is zeroed by the trailing zki of the PREVIOUS call (main stream), which evFork orders before us.
    cudaEventRecord(evFork, 0);
    cudaStreamWaitEvent(s2, evFork, 0);
    histK   <<<eb, 256, 0, s2>>>(ei + E, cnt, E, ET);                      // launch 1
    scanAll <<<1, 1024, 0, s2>>>(cnt, rowptr, cnt, n);                     // launch 2
    scatterK<<<eb, 256, 0, s2>>>(ei, ei + E, cnt, csrsrc, E, ET);          // launch 3
    cudaEventRecord(evJoin, s2);

    // ---------------- layer 0 (main stream, runs concurrently with CSR) ----------------
    gemm128_tc<<<gb, 256>>>(x, W0, as0, ad0, h, als, ald, n);              // launch 4 (ncu target)
    cudaStreamWaitEvent(0, evJoin, 0);
    gat_edge4<<<ab5, 512>>>(rowptr, csrsrc, als, ald, h, agg, b0, g0, be0, m0, v0, n);

    // ---------------- layer 1 ----------------
    gemm128_tc<<<gb, 256>>>(agg, W1, as1, ad1, h, als, ald, n);
    gat_edge4<<<ab5, 512>>>(rowptr, csrsrc, als, ald, h, agg, b1, g1, be1, m1, v1, n);

    // ---------------- layer 2 (heads=1, 40 classes) ----------------
    gemm40<<<1184, 256>>>(agg, W2, as2, ad2, h, als, ald, n);
    gat_edge1<<<ab5, 512>>>(rowptr, csrsrc, als, ald, h, b2, (float*)d_out, n);

    // re-zero cnt for the NEXT call (main stream; ordered before next call's histK via evFork)
    zki<<<cb, 256>>>(cnt, n);
}

// round 17
// speedup vs baseline: 2.3708x; 1.1108x over previous
#include <cuda_runtime.h>
#include <math.h>

#define NFEAT  128
#define HIDF   128
#define HEADS  4
#define NHID   32
#define NCLASS 40
#define NEGS   0.2f
#define EPSBN  1e-5f
#define MAXN   100000
#define MAXET  1700000   // E (1.6M) + N (100K) self-loops

// ---------------- scratch (static device globals; no allocation) ----------------
__device__ float g_h   [(size_t)MAXN * HIDF];   // projected features (reused as h2 [N,40])
__device__ float g_agg [(size_t)MAXN * HIDF];   // aggregation output / next-layer input
__device__ float g_als [(size_t)MAXN * HEADS];
__device__ float g_ald [(size_t)MAXN * HEADS];
__device__ int   g_rowptr[MAXN + 1];
__device__ int   g_cnt   [MAXN];                // hist buffer / scatter cursor (zeroed by zki at call end)
__device__ int   g_csrsrc[MAXET];
__device__ float g_whi0[16384], g_wlo0[16384];  // pre-split W0 (tf32 hi/lo)
__device__ float g_whi1[16384], g_wlo1[16384];  // pre-split W1

__device__ __forceinline__ float lrelu(float e) { return e > 0.f ? e : NEGS * e; }

__device__ __forceinline__ float wredmax(float v) {
#pragma unroll
    for (int o = 16; o >= 1; o >>= 1) v = fmaxf(v, __shfl_xor_sync(0xffffffffu, v, o));
    return v;
}
__device__ __forceinline__ float wredsum(float v) {
#pragma unroll
    for (int o = 16; o >= 1; o >>= 1) v += __shfl_xor_sync(0xffffffffu, v, o);
    return v;
}

__device__ __forceinline__ unsigned f2tf(float x) {
    unsigned r;
    asm("cvt.rna.tf32.f32 %0, %1;" : "=r"(r) : "f"(x));
    return r;
}

__device__ __forceinline__ void mma_tf32(float* c, const unsigned* a, const unsigned* b) {
    asm volatile(
        "mma.sync.aligned.m16n8k8.row.col.f32.tf32.tf32.f32 "
        "{%0,%1,%2,%3},{%4,%5,%6,%7},{%8,%9},{%0,%1,%2,%3};"
        : "+f"(c[0]), "+f"(c[1]), "+f"(c[2]), "+f"(c[3])
        : "r"(a[0]), "r"(a[1]), "r"(a[2]), "r"(a[3]), "r"(b[0]), "r"(b[1]));
}

// ---------------- zero fill (ints) ----------------
__global__ void zki(int* __restrict__ p, int cnt) {
    int i = blockIdx.x * blockDim.x + threadIdx.x;
    int stride = gridDim.x * blockDim.x;
    for (; i < cnt; i += stride) p[i] = 0;
}

// ---------------- W pre-split: W -> (tf32 hi, tf32 lo) ----------------
__global__ void wsplitK(const float* __restrict__ W, float* __restrict__ hi,
                        float* __restrict__ lo) {
    int i = blockIdx.x * blockDim.x + threadIdx.x;   // 64 blocks x 256 = 16384
    float w = W[i];
    float h = __uint_as_float(f2tf(w));
    hi[i] = h;
    lo[i] = __uint_as_float(f2tf(w - h));
}

// ---------------- CSR build (multi-block, proven) ----------------
__global__ void histK(const int* __restrict__ dst, int* __restrict__ hist, int E, int ET) {
    int i = blockIdx.x * blockDim.x + threadIdx.x;
    int stride = gridDim.x * blockDim.x;
    for (; i < ET; i += stride) {
        int d = (i < E) ? dst[i] : (i - E);
        atomicAdd(&hist[d], 1);
    }
}

// single-block blocked exclusive scan; writes rowptr[0..n] and seeds cnt[i]=rowptr[i].
__global__ void scanAll(const int* __restrict__ hist, int* __restrict__ rowptr,
                        int* __restrict__ cnt, int n) {
    __shared__ int tsum[1024];
    int t = threadIdx.x;
    int C = (n + 1023) >> 10;
    int b = t * C;
    int e = min(b + C, n);
    int s = 0;
    for (int i = b; i < e; i++) s += hist[i];
    tsum[t] = s;
    __syncthreads();
#pragma unroll
    for (int off = 1; off < 1024; off <<= 1) {
        int t2 = (t >= off) ? tsum[t - off] : 0;
        __syncthreads();
        tsum[t] += t2;
        __syncthreads();
    }
    int run = tsum[t] - s;   // exclusive base
    for (int i = b; i < e; i++) {
        int hv = hist[i];
        rowptr[i] = run;
        cnt[i] = run;        // aliases hist; read hv first
        run += hv;
    }
    if (e == n && b < n) rowptr[n] = run;
}

__global__ void scatterK(const int* __restrict__ src, const int* __restrict__ dst,
                         int* __restrict__ cnt, int* __restrict__ csrsrc, int E, int ET) {
    int i = blockIdx.x * blockDim.x + threadIdx.x;
    int stride = gridDim.x * blockDim.x;
    for (; i < ET; i += stride) {
        int s, d;
        if (i < E) { s = src[i]; d = dst[i]; } else { s = d = i - E; }
        int pos = atomicAdd(&cnt[d], 1);
        csrsrc[pos] = s;
    }
}

// ---------------- tensor-core GEMM (3xTF32, pre-split W) + fused attention logits ----------------
#define KC   16
#define KST  20
__global__ void __launch_bounds__(256, 2)
gemm128_tc(const float* __restrict__ X, const float* __restrict__ Whi,
           const float* __restrict__ Wlo,
           const float* __restrict__ as, const float* __restrict__ ad,
           float* __restrict__ O, float* __restrict__ als, float* __restrict__ ald,
           int n) {
    __shared__ float Ahi[128 * KST], Alo[128 * KST];
    __shared__ float Bhi[128 * KST], Blo[128 * KST];
    __shared__ float asSh[128], adSh[128];

    int t    = threadIdx.x;
    int lane = t & 31;
    int wid  = t >> 5;
    int wm   = wid >> 1;
    int wn   = wid & 1;
    int gid  = lane >> 2;
    int tig  = lane & 3;
    int row0 = blockIdx.x * 128;

    if (t < 128) { asSh[t] = as[t]; adSh[t] = ad[t]; }

    float acc[2][8][4];
#pragma unroll
    for (int i = 0; i < 2; i++)
#pragma unroll
        for (int j = 0; j < 8; j++)
#pragma unroll
            for (int k = 0; k < 4; k++) acc[i][j][k] = 0.f;

    for (int kt = 0; kt < 128; kt += KC) {
#pragma unroll
        for (int half = 0; half < 2; half++) {
            int r  = (t >> 2) + half * 64;
            int kq = (t & 3) * 4;
            int gr = row0 + r;
            // X: load + split in-kernel
            float4 xv = (gr < n) ? *(const float4*)(X + (size_t)gr * 128 + kt + kq)
                                 : make_float4(0.f, 0.f, 0.f, 0.f);
            float xa[4] = {xv.x, xv.y, xv.z, xv.w};
            float xh[4], xl[4];
#pragma unroll
            for (int j = 0; j < 4; j++) {
                xh[j] = __uint_as_float(f2tf(xa[j]));
                xl[j] = __uint_as_float(f2tf(xa[j] - xh[j]));
            }
            *(float4*)&Ahi[r * KST + kq] = make_float4(xh[0], xh[1], xh[2], xh[3]);
            *(float4*)&Alo[r * KST + kq] = make_float4(xl[0], xl[1], xl[2], xl[3]);
            // W: pre-split, straight copy
            *(float4*)&Bhi[r * KST + kq] = *(const float4*)(Whi + (size_t)r * 128 + kt + kq);
            *(float4*)&Blo[r * KST + kq] = *(const float4*)(Wlo + (size_t)r * 128 + kt + kq);
        }
        __syncthreads();

#pragma unroll
        for (int ks = 0; ks < KC; ks += 8) {
            unsigned ah[2][4], al[2][4];
#pragma unroll
            for (int tm = 0; tm < 2; tm++) {
                int r = wm * 32 + tm * 16 + gid;
                ah[tm][0] = __float_as_uint(Ahi[r * KST + ks + tig]);
                ah[tm][1] = __float_as_uint(Ahi[(r + 8) * KST + ks + tig]);
                ah[tm][2] = __float_as_uint(Ahi[r * KST + ks + tig + 4]);
                ah[tm][3] = __float_as_uint(Ahi[(r + 8) * KST + ks + tig + 4]);
                al[tm][0] = __float_as_uint(Alo[r * KST + ks + tig]);
                al[tm][1] = __float_as_uint(Alo[(r + 8) * KST + ks + tig]);
                al[tm][2] = __float_as_uint(Alo[r * KST + ks + tig + 4]);
                al[tm][3] = __float_as_uint(Alo[(r + 8) * KST + ks + tig + 4]);
            }
            unsigned bh[8][2], bl[8][2];
#pragma unroll
            for (int tn = 0; tn < 8; tn++) {
                int c = wn * 64 + tn * 8 + gid;
                bh[tn][0] = __float_as_uint(Bhi[c * KST + ks + tig]);
                bh[tn][1] = __float_as_uint(Bhi[c * KST + ks + tig + 4]);
                bl[tn][0] = __float_as_uint(Blo[c * KST + ks + tig]);
                bl[tn][1] = __float_as_uint(Blo[c * KST + ks + tig + 4]);
            }
            // term-outer ordering: consecutive MMAs target different accumulators
#pragma unroll
            for (int tm = 0; tm < 2; tm++)
#pragma unroll
                for (int tn = 0; tn < 8; tn++)
                    mma_tf32(acc[tm][tn], ah[tm], bh[tn]);
#pragma unroll
            for (int tm = 0; tm < 2; tm++)
#pragma unroll
                for (int tn = 0; tn < 8; tn++)
                    mma_tf32(acc[tm][tn], ah[tm], bl[tn]);
#pragma unroll
            for (int tm = 0; tm < 2; tm++)
#pragma unroll
                for (int tn = 0; tn < 8; tn++)
                    mma_tf32(acc[tm][tn], al[tm], bh[tn]);
        }
        __syncthreads();
    }

    // store O
#pragma unroll
    for (int tm = 0; tm < 2; tm++) {
        int r = row0 + wm * 32 + tm * 16 + gid;
#pragma unroll
        for (int tn = 0; tn < 8; tn++) {
            int c = wn * 64 + tn * 8 + 2 * tig;
            if (r < n)
                *(float2*)(O + (size_t)r * 128 + c) = make_float2(acc[tm][tn][0], acc[tm][tn][1]);
            if (r + 8 < n)
                *(float2*)(O + (size_t)(r + 8) * 128 + c) = make_float2(acc[tm][tn][2], acc[tm][tn][3]);
        }
    }

    // fused attention logits: warp wn owns heads {2wn, 2wn+1}
    float ps[2][4], pd[2][4];
#pragma unroll
    for (int j = 0; j < 2; j++)
#pragma unroll
        for (int sl = 0; sl < 4; sl++) { ps[j][sl] = 0.f; pd[j][sl] = 0.f; }
#pragma unroll
    for (int tm = 0; tm < 2; tm++)
#pragma unroll
        for (int tn = 0; tn < 8; tn++) {
            int j = tn >> 2;
            int c = wn * 64 + tn * 8 + 2 * tig;
            float a0 = asSh[c], a1 = asSh[c + 1];
            float d0 = adSh[c], d1 = adSh[c + 1];
            ps[j][tm * 2 + 0] += acc[tm][tn][0] * a0 + acc[tm][tn][1] * a1;
            ps[j][tm * 2 + 1] += acc[tm][tn][2] * a0 + acc[tm][tn][3] * a1;
            pd[j][tm * 2 + 0] += acc[tm][tn][0] * d0 + acc[tm][tn][1] * d1;
            pd[j][tm * 2 + 1] += acc[tm][tn][2] * d0 + acc[tm][tn][3] * d1;
        }
#pragma unroll
    for (int j = 0; j < 2; j++)
#pragma unroll
        for (int sl = 0; sl < 4; sl++) {
            ps[j][sl] += __shfl_xor_sync(0xffffffffu, ps[j][sl], 1);
            ps[j][sl] += __shfl_xor_sync(0xffffffffu, ps[j][sl], 2);
            pd[j][sl] += __shfl_xor_sync(0xffffffffu, pd[j][sl], 1);
            pd[j][sl] += __shfl_xor_sync(0xffffffffu, pd[j][sl], 2);
        }
    if (tig == 0) {
#pragma unroll
        for (int sl = 0; sl < 4; sl++) {
            int r = row0 + wm * 32 + (sl >> 1) * 16 + (sl & 1) * 8 + gid;
            if (r < n) {
#pragma unroll
                for (int j = 0; j < 2; j++) {
                    als[(size_t)r * 4 + 2 * wn + j] = ps[j][sl];
                    ald[(size_t)r * 4 + 2 * wn + j] = pd[j][sl];
                }
            }
        }
    }
}

// ---------------- fused GAT edge stage, 4 heads — at the LTS gather floor (FROZEN) ----------------
__global__ void __launch_bounds__(512)
gat_edge4(const int* __restrict__ rowptr, const int* __restrict__ csrsrc,
          const float* __restrict__ als, const float* __restrict__ ald,
          const float* __restrict__ h, float* __restrict__ out,
          const float* __restrict__ bias, const float* __restrict__ gam,
          const float* __restrict__ bet, const float* __restrict__ mu,
          const float* __restrict__ var, int n) {
    int lane = threadIdx.x & 31;
    int d = (blockIdx.x * blockDim.x + threadIdx.x) >> 5;
    if (d >= n) return;

    int start = rowptr[d], end = rowptr[d + 1];
    float4 bld = ((const float4*)ald)[d];
    int head = lane >> 3;
    float bh = (head == 0) ? bld.x : (head == 1) ? bld.y : (head == 2) ? bld.z : bld.w;

    float4 acc = make_float4(0.f, 0.f, 0.f, 0.f);
    float sw = 0.f;
#pragma unroll 8
    for (int e = start; e < end; e++) {
        int s = csrsrc[e];                              // broadcast (same addr all lanes)
        float av = __ldg(als + (size_t)s * 4 + head);   // broadcast per 8 lanes
        float w = __expf(lrelu(av + bh));
        sw += w;
        float4 hv = ((const float4*)h)[(size_t)s * 32 + lane];
        acc.x += w * hv.x; acc.y += w * hv.y;
        acc.z += w * hv.z; acc.w += w * hv.w;
    }
    float inv = __frcp_rn(sw);

    // epilogue: normalize, +bias, BN(eval), ReLU
    float4 bb = ((const float4*)bias)[lane];
    float4 gg = ((const float4*)gam)[lane];
    float4 be = ((const float4*)bet)[lane];
    float4 mm = ((const float4*)mu)[lane];
    float4 vv = ((const float4*)var)[lane];
    float4 o;
    o.x = (acc.x * inv + bb.x - mm.x) * rsqrtf(vv.x + EPSBN) * gg.x + be.x;
    o.y = (acc.y * inv + bb.y - mm.y) * rsqrtf(vv.y + EPSBN) * gg.y + be.y;
    o.z = (acc.z * inv + bb.z - mm.z) * rsqrtf(vv.z + EPSBN) * gg.z + be.z;
    o.w = (acc.w * inv + bb.w - mm.w) * rsqrtf(vv.w + EPSBN) * gg.w + be.w;
    o.x = fmaxf(o.x, 0.f); o.y = fmaxf(o.y, 0.f);
    o.z = fmaxf(o.z, 0.f); o.w = fmaxf(o.w, 0.f);
    ((float4*)(out + (size_t)d * 128))[lane] = o;
}

// ---------------- layer-2 GEMM (128 -> 40) fused with attention logits, 4-way ILP ----------------
__global__ void gemm40(const float* __restrict__ X, const float* __restrict__ W,
                       const float* __restrict__ as2, const float* __restrict__ ad2,
                       float* __restrict__ H2, float* __restrict__ als,
                       float* __restrict__ ald, int n) {
    __shared__ float Ws[NCLASS][132];
    __shared__ float asS[NCLASS], adS[NCLASS];
    __shared__ float xs[8][128];
    int t = threadIdx.x;
    for (int i = t; i < NCLASS * 128; i += blockDim.x) {
        int c = i >> 7, k = i & 127;
        Ws[c][k] = W[i];
    }
    if (t < NCLASS) { asS[t] = as2[t]; adS[t] = ad2[t]; }
    __syncthreads();

    int wid = t >> 5, lane = t & 31;
    int wtotal = (gridDim.x * blockDim.x) >> 5;
    for (int row = blockIdx.x * 8 + wid; row < n; row += wtotal) {
        float4 xv = ((const float4*)(X + (size_t)row * 128))[lane];
        ((float4*)xs[wid])[lane] = xv;
        __syncwarp();
        int c0 = lane, c1 = 32 + lane;
        // 4 independent accumulator chains per output
        float p[4] = {0.f, 0.f, 0.f, 0.f};
        float q[4] = {0.f, 0.f, 0.f, 0.f};
#pragma unroll
        for (int k = 0; k < 128; k += 16) {
#pragma unroll
            for (int j = 0; j < 4; j++) {
                float4 xk = *(const float4*)&xs[wid][k + j * 4];
                float4 w0 = *(const float4*)&Ws[c0][k + j * 4];
                p[j] += xk.x * w0.x + xk.y * w0.y + xk.z * w0.z + xk.w * w0.w;
                if (lane < 8) {
                    float4 w1 = *(const float4*)&Ws[c1][k + j * 4];
                    q[j] += xk.x * w1.x + xk.y * w1.y + xk.z * w1.z + xk.w * w1.w;
                }
            }
        }
        float acc0 = (p[0] + p[1]) + (p[2] + p[3]);
        float acc1 = (q[0] + q[1]) + (q[2] + q[3]);
        H2[(size_t)row * NCLASS + c0] = acc0;
        if (lane < 8) H2[(size_t)row * NCLASS + c1] = acc1;
        float ps = acc0 * asS[c0] + (lane < 8 ? acc1 * asS[c1] : 0.f);
        float pd = acc0 * adS[c0] + (lane < 8 ? acc1 * adS[c1] : 0.f);
        ps = wredsum(ps);
        pd = wredsum(pd);
        if (lane == 0) { als[row] = ps; ald[row] = pd; }
        __syncwarp();
    }
}

// ---------------- fused layer-2 edge stage (1 head) — single pass + bias + log_softmax ----------------
__global__ void __launch_bounds__(512)
gat_edge1(const int* __restrict__ rowptr, const int* __restrict__ csrsrc,
          const float* __restrict__ als, const float* __restrict__ ald,
          const float* __restrict__ h2, const float* __restrict__ b2,
          float* __restrict__ out, int n) {
    int lane = threadIdx.x & 31;
    int d = (blockIdx.x * blockDim.x + threadIdx.x) >> 5;
    if (d >= n) return;

    int start = rowptr[d], end = rowptr[d + 1];
    float bld = ald[d];

    float acc0 = 0.f, acc1 = 0.f, sw = 0.f;
#pragma unroll 8
    for (int e = start; e < end; e++) {
        int s = csrsrc[e];                       // broadcast
        float w = __expf(lrelu(als[s] + bld));
        sw += w;
        const float* row = h2 + (size_t)s * NCLASS;
        acc0 += w * row[lane];
        if (lane < 8) acc1 += w * row[32 + lane];
    }
    float inv = __frcp_rn(sw);

    // bias + log_softmax
    float x0 = acc0 * inv + b2[lane];
    float x1 = (lane < 8) ? acc1 * inv + b2[32 + lane] : -3.4e38f;
    float m = wredmax(fmaxf(x0, x1));
    float s = __expf(x0 - m) + (lane < 8 ? __expf(x1 - m) : 0.f);
    s = wredsum(s);
    float lse = logf(s);
    float* orow = out + (size_t)d * NCLASS;
    orow[lane] = x0 - m - lse;
    if (lane < 8) orow[32 + lane] = x1 - m - lse;
}

// ---------------- host ----------------
extern "C" void kernel_launch(void* const* d_in, const int* in_sizes, int n_in,
                              void* d_out, int out_size) {
    const float* x   = (const float*)d_in[0];
    const int*   ei  = (const int*)d_in[1];
    const float* W0  = (const float*)d_in[2];
    const float* as0 = (const float*)d_in[3];
    const float* ad0 = (const float*)d_in[4];
    const float* b0  = (const float*)d_in[5];
    const float* g0  = (const float*)d_in[6];
    const float* be0 = (const float*)d_in[7];
    const float* m0  = (const float*)d_in[8];
    const float* v0  = (const float*)d_in[9];
    const float* W1  = (const float*)d_in[10];
    const float* as1 = (const float*)d_in[11];
    const float* ad1 = (const float*)d_in[12];
    const float* b1  = (const float*)d_in[13];
    const float* g1  = (const float*)d_in[14];
    const float* be1 = (const float*)d_in[15];
    const float* m1  = (const float*)d_in[16];
    const float* v1  = (const float*)d_in[17];
    const float* W2  = (const float*)d_in[18];
    const float* as2 = (const float*)d_in[19];
    const float* ad2 = (const float*)d_in[20];
    const float* b2  = (const float*)d_in[21];

    int n  = in_sizes[0] / NFEAT;
    int E  = in_sizes[1] / 2;
    int ET = E + n;

    float *h, *agg, *als, *ald, *whi0, *wlo0, *whi1, *wlo1;
    int *rowptr, *cnt, *csrsrc;
    cudaGetSymbolAddress((void**)&h, g_h);
    cudaGetSymbolAddress((void**)&agg, g_agg);
    cudaGetSymbolAddress((void**)&als, g_als);
    cudaGetSymbolAddress((void**)&ald, g_ald);
    cudaGetSymbolAddress((void**)&rowptr, g_rowptr);
    cudaGetSymbolAddress((void**)&cnt, g_cnt);
    cudaGetSymbolAddress((void**)&csrsrc, g_csrsrc);
    cudaGetSymbolAddress((void**)&whi0, g_whi0);
    cudaGetSymbolAddress((void**)&wlo0, g_wlo0);
    cudaGetSymbolAddress((void**)&whi1, g_whi1);
    cudaGetSymbolAddress((void**)&wlo1, g_wlo1);

    // lazily-created side stream + fork/join events (resources, not device memory)
    static cudaStream_t s2 = 0;
    static cudaEvent_t evFork = 0, evJoin = 0;
    if (!s2) {
        cudaStreamCreateWithFlags(&s2, cudaStreamNonBlocking);
        cudaEventCreateWithFlags(&evFork, cudaEventDisableTiming);
        cudaEventCreateWithFlags(&evJoin, cudaEventDisableTiming);
    }

    const int gb  = (n + 127) / 128;           // gemm blocks
    const int ab5 = (n + 15) / 16;             // warp-per-node blocks (512 thr)
    const int eb  = (ET + 255) / 256;          // thread-per-edge blocks
    const int cb  = (n + 255) / 256;

    // ---------------- fork: CSR build on side stream (cnt zeroed by previous call's zki) ----------------
    cudaEventRecord(evFork, 0);
    cudaStreamWaitEvent(s2, evFork, 0);
    histK<<<eb, 256, 0, s2>>>(ei + E, cnt, E, ET);                         // launch 1
    // W pre-split on main stream (needed by gemm0/gemm1 on main)
    wsplitK<<<64, 256>>>(W0, whi0, wlo0);                                  // launch 2
    wsplitK<<<64, 256>>>(W1, whi1, wlo1);                                  // launch 3
    scanAll<<<1, 1024, 0, s2>>>(cnt, rowptr, cnt, n);                      // launch 4 (ncu target)
    scatterK<<<eb, 256, 0, s2>>>(ei, ei + E, cnt, csrsrc, E, ET);          // launch 5
    cudaEventRecord(evJoin, s2);

    // ---------------- layer 0 (main stream, runs concurrently with CSR) ----------------
    gemm128_tc<<<gb, 256>>>(x, whi0, wlo0, as0, ad0, h, als, ald, n);      // launch 6
    cudaStreamWaitEvent(0, evJoin, 0);
    gat_edge4<<<ab5, 512>>>(rowptr, csrsrc, als, ald, h, agg, b0, g0, be0, m0, v0, n);

    // ---------------- layer 1 ----------------
    gemm128_tc<<<gb, 256>>>(agg, whi1, wlo1, as1, ad1, h, als, ald, n);
    gat_edge4<<<ab5, 512>>>(rowptr, csrsrc, als, ald, h, agg, b1, g1, be1, m1, v1, n);

    // ---------------- layer 2 (heads=1, 40 classes) ----------------
    gemm40<<<1184, 256>>>(agg, W2, as2, ad2, h, als, ald, n);
    gat_edge1<<<ab5, 512>>>(rowptr, csrsrc, als, ald, h, b2, (float*)d_out, n);

    // re-zero cnt for the NEXT call (main stream; ordered before next call's histK via evFork)
    zki<<<cb, 256>>>(cnt, n);
}